// round 5
// baseline (speedup 1.0000x reference)
#include <cuda_runtime.h>
#include <cstdint>

#define NTOK 49
#define CDIM 128
#define THREADS 512

// ---- persistent prepped buffers (filled by prep kernels each launch) ----
__device__ float g_qkvw[3 * 128 * 132];        // tf32, B-frag order, q-scale folded
__device__ float g_projw[128 * 132];           // tf32, B-frag order
__device__ float g_qkvb[512];                  // qkv_b (q part scaled) + proj_b
__device__ float g_bm[64 * 4 * 49 * 56];       // bias_table gather + mask, fused

// ---- shared memory regions (float offsets) ----
// S_QK holds: q-frags (8192) in ph2-3, P-frags (14336) in ph4-5 (overlaps dead KF),
//             out-stage [64][132]=8448 in ph6.
#define S_A   0          // 8192  : x A-frags, later o A-frags
#define S_W   8192       // 16896 : weight tile [128][132] OR attn [4][64*60]
#define S_QK  25088
#define S_KF  33280      // k frags: [4*64][36]  (EVEN stride -> aligned LDS.64)
#define S_V   42496      // v frags: [4*32][58]  (EVEN stride -> aligned LDS.64)
#define S_B   49920      // biases 512
#define SMEMF 50432      // 201728 bytes

__device__ __forceinline__ float f2tf(float f) {
    uint32_t u;
    asm("cvt.rna.tf32.f32 %0, %1;" : "=r"(u) : "f"(f));
    return __uint_as_float(u);
}
__device__ __forceinline__ uint32_t fau(float f) { return __float_as_uint(f); }

__device__ __forceinline__ void mma8(float c[4], const uint32_t a[4], const uint32_t b[2]) {
    asm volatile(
        "mma.sync.aligned.m16n8k8.row.col.f32.tf32.tf32.f32 "
        "{%0,%1,%2,%3},{%4,%5,%6,%7},{%8,%9},{%0,%1,%2,%3};\n"
        : "+f"(c[0]), "+f"(c[1]), "+f"(c[2]), "+f"(c[3])
        : "r"(a[0]), "r"(a[1]), "r"(a[2]), "r"(a[3]), "r"(b[0]), "r"(b[1]));
}

// ================= prep kernels (run once per launch) =================
__global__ void prep_weights(const float* __restrict__ qkv_w, const float* __restrict__ qkv_b,
                             const float* __restrict__ proj_w, const float* __restrict__ proj_b)
{
    int idx = blockIdx.x * 256 + threadIdx.x;
    const float scale = 0.17677669529663687f;   // 32^-0.5
    if (idx < 49152) {
        int ch = idx >> 14;
        int c  = (idx >> 7) & 127;
        int j  = idx & 127;
        int ks = j >> 3, rem = j & 7, t = rem >> 1, half = rem & 1;
        float v = qkv_w[(size_t)(ch * 128 + c) * 128 + 8 * ks + t + 4 * half];
        if (ch == 0) v *= scale;
        g_qkvw[ch * 16896 + c * 132 + j] = f2tf(v);
    } else if (idx < 65536) {
        int i2 = idx - 49152;
        int c = i2 >> 7, j = i2 & 127;
        int ks = j >> 3, rem = j & 7, t = rem >> 1, half = rem & 1;
        g_projw[c * 132 + j] = f2tf(proj_w[(size_t)c * 128 + 8 * ks + t + 4 * half]);
    } else if (idx < 65536 + 384) {
        int i = idx - 65536;
        float v = qkv_b[i];
        if (i < 128) v *= scale;
        g_qkvb[i] = v;
    } else if (idx < 65536 + 512) {
        int i = idx - 65536;
        g_qkvb[i] = proj_b[i - 384];
    }
}

__global__ void prep_bm(const float* __restrict__ mask, const float* __restrict__ bias_table)
{
    int idx = blockIdx.x * 256 + threadIdx.x;
    if (idx >= 64 * 4 * 49 * 56) return;
    int j = idx % 56;
    int rest = idx / 56;
    int i = rest % 49; rest /= 49;
    int h = rest & 3;
    int w = rest >> 2;
    float v = 0.f;
    if (j < 49) {
        int ih = i / 7, iw = i - 7 * ih;
        int jh = j / 7, jw = j - 7 * jh;
        int ridx = (ih - jh + 6) * 13 + (iw - jw + 6);
        v = bias_table[ridx * 4 + h] + mask[(size_t)(w * 49 + i) * 49 + j];
    }
    g_bm[idx] = v;
}

// ================= main kernel =================
__global__ __launch_bounds__(THREADS, 1)
void wattn(const float* __restrict__ x, float* __restrict__ out)
{
    extern __shared__ float s[];
    const int tid  = threadIdx.x;
    const int wid  = tid >> 5;
    const int lane = tid & 31;
    const int g    = lane >> 2;
    const int t    = lane & 3;
    const int b    = blockIdx.x;
    const int mi   = wid & 3;
    const int nq   = wid >> 2;

    // ---- Phase 1: x -> A-frag layout (tf32, zero-padded rows), stage biases ----
    {
        const float4* xb = (const float4*)(x + (size_t)b * (NTOK * CDIM));
        for (int i = tid; i < 2048; i += THREADS) {
            int r = i >> 5, c4 = i & 31;
            float4 v = (r < NTOK) ? xb[r * 32 + c4] : make_float4(0.f, 0.f, 0.f, 0.f);
            int mm = r >> 4, gg = r & 7, half = (r >> 3) & 1, ks = c4 >> 1, chalf = c4 & 1;
            float* d = s + S_A + ((mm * 16 + ks) * 32 + gg * 4) * 4 + half + 2 * chalf;
            d[0]  = f2tf(v.x);
            d[4]  = f2tf(v.y);
            d[8]  = f2tf(v.z);
            d[12] = f2tf(v.w);
        }
        s[S_B + tid] = g_qkvb[tid];   // THREADS == 512 == bias count
    }
    __syncthreads();

    // ---- Phase 2: QKV GEMM (3 chunks of 128 cols), frag-layout epilogues ----
    for (int ch = 0; ch < 3; ch++) {
        {
            const float4* src = (const float4*)(g_qkvw + ch * 16896);
            float4* dst = (float4*)(s + S_W);
            for (int i = tid; i < 4224; i += THREADS) dst[i] = src[i];
        }
        __syncthreads();

        float acc[4][4];
#pragma unroll
        for (int i = 0; i < 4; i++)
#pragma unroll
            for (int j = 0; j < 4; j++) acc[i][j] = 0.f;

        const float4* ap = (const float4*)(s + S_A) + mi * 512 + lane;
        const float* wcol = s + S_W + (nq * 32 + g) * 132 + t * 2;
#pragma unroll
        for (int ks = 0; ks < 16; ks++) {
            float4 av = ap[ks * 32];
            uint32_t a[4] = { fau(av.x), fau(av.y), fau(av.z), fau(av.w) };
#pragma unroll
            for (int nt = 0; nt < 4; nt++) {
                float2 bv = *(const float2*)(wcol + nt * (8 * 132) + ks * 8);
                uint32_t bb[2] = { fau(bv.x), fau(bv.y) };
                mma8(acc[nt], a, bb);
            }
        }

        // epilogue: scatter to q/k/v fragment layouts
        const int r0 = mi * 16 + g;
#pragma unroll
        for (int nt = 0; nt < 4; nt++) {
            const int c0 = nq * 32 + nt * 8 + 2 * t;
#pragma unroll
            for (int e = 0; e < 4; e++) {
                int rr = r0 + ((e >> 1) << 3);
                int cc = c0 + (e & 1);
                float val = acc[nt][e] + s[S_B + ch * 128 + cc];
                int h = cc >> 5, dd = cc & 31;
                if (ch == 0) {
                    s[S_QK + ((h * 4 + (rr >> 4)) * 4 + (dd >> 3)) * 128
                           + ((rr & 7) * 4 + (dd & 3)) * 4 + ((rr >> 3) & 1) + 2 * ((dd >> 2) & 1)]
                        = f2tf(val);
                } else if (ch == 1) {
                    s[S_KF + (h * 64 + rr) * 36 + (dd >> 3) * 8 + (dd & 3) * 2 + ((dd >> 2) & 1)]
                        = f2tf(val);
                } else {
                    if (rr < 56)
                        s[S_V + (h * 32 + dd) * 58 + (rr >> 3) * 8 + (rr & 3) * 2 + ((rr >> 2) & 1)]
                            = f2tf(val);
                }
            }
        }
        __syncthreads();
    }

    // ---- Phase 3: scores = q k^T ; add fused bias+mask from g_bm ----
    {
        const int h = wid >> 2, m3 = wid & 3;
        float acc[7][4];
#pragma unroll
        for (int i = 0; i < 7; i++)
#pragma unroll
            for (int j = 0; j < 4; j++) acc[i][j] = 0.f;

        const float4* ap = (const float4*)(s + S_QK) + (h * 4 + m3) * 128 + lane;
        const float* kcol = s + S_KF + (h * 64 + g) * 36 + t * 2;
#pragma unroll
        for (int ks = 0; ks < 4; ks++) {
            float4 av = ap[ks * 32];
            uint32_t a[4] = { fau(av.x), fau(av.y), fau(av.z), fau(av.w) };
#pragma unroll
            for (int nt = 0; nt < 7; nt++) {
                float2 bv = *(const float2*)(kcol + nt * (8 * 36) + ks * 8);
                uint32_t bb[2] = { fau(bv.x), fau(bv.y) };
                mma8(acc[nt], a, bb);
            }
        }

        const float* bmw = g_bm + (size_t)(b & 63) * (4 * 49 * 56);
        const int r0 = m3 * 16 + g;
        float* at = s + S_W + h * 3840;
#pragma unroll
        for (int nt = 0; nt < 7; nt++) {
            const int c0 = nt * 8 + 2 * t;
#pragma unroll
            for (int e = 0; e < 4; e++) {
                int rr = r0 + ((e >> 1) << 3);
                int jj = c0 + (e & 1);
                if (rr < NTOK && jj < NTOK)
                    at[rr * 60 + jj] = acc[nt][e] + __ldg(bmw + (h * NTOK + rr) * 56 + jj);
            }
        }
    }
    __syncthreads();

    // ---- Phase 4: softmax rows (h,i); write P fragments (overwrites q/k region) ----
    if (tid < 4 * NTOK) {
        const int h = tid / NTOK;
        const int i = tid - h * NTOK;
        const float* row = s + S_W + h * 3840 + i * 60;
        float m = row[0];
#pragma unroll
        for (int j = 1; j < NTOK; j++) m = fmaxf(m, row[j]);
        float ssum = 0.f;
#pragma unroll
        for (int j = 0; j < NTOK; j++) ssum += __expf(row[j] - m);
        const float inv = 1.0f / ssum;
        const int mm = i >> 4, gg = i & 7, half = (i >> 3) & 1;
#pragma unroll
        for (int j = 0; j < 56; j++) {
            float pv = (j < NTOK) ? __expf(row[j] - m) * inv : 0.f;
            s[S_QK + ((h * 4 + mm) * 7 + (j >> 3)) * 128
                   + (gg * 4 + (j & 3)) * 4 + half + 2 * ((j >> 2) & 1)] = f2tf(pv);
        }
    }
    __syncthreads();

    // ---- Phase 5: o = P @ V ; write o A-frags into S_A (x dead) ----
    {
        const int h = wid >> 2, m5 = wid & 3;
        float acc[4][4];
#pragma unroll
        for (int i = 0; i < 4; i++)
#pragma unroll
            for (int j = 0; j < 4; j++) acc[i][j] = 0.f;

        const float4* ap = (const float4*)(s + S_QK) + (h * 4 + m5) * 224 + lane;
        const float* vcol = s + S_V + (h * 32 + g) * 58 + t * 2;
#pragma unroll
        for (int ks = 0; ks < 7; ks++) {
            float4 av = ap[ks * 32];
            uint32_t a[4] = { fau(av.x), fau(av.y), fau(av.z), fau(av.w) };
#pragma unroll
            for (int nt = 0; nt < 4; nt++) {
                float2 bv = *(const float2*)(vcol + nt * (8 * 58) + ks * 8);
                uint32_t bb[2] = { fau(bv.x), fau(bv.y) };
                mma8(acc[nt], a, bb);
            }
        }

        const int r0 = m5 * 16 + g;
#pragma unroll
        for (int nt = 0; nt < 4; nt++) {
            const int d0 = nt * 8 + 2 * t;
#pragma unroll
            for (int e = 0; e < 4; e++) {
                int rr = r0 + ((e >> 1) << 3);
                int dd = d0 + (e & 1);
                int c  = h * 32 + dd;
                s[S_A + ((rr >> 4) * 16 + (c >> 3)) * 128
                      + ((rr & 7) * 4 + (c & 3)) * 4 + ((rr >> 3) & 1) + 2 * ((c >> 2) & 1)]
                    = f2tf(acc[nt][e]);
            }
        }
    }
    __syncthreads();

    // ---- Phase 6: final = o @ proj_w^T + proj_b ----
    {
        const float4* src = (const float4*)g_projw;
        float4* dst = (float4*)(s + S_W);
        for (int i = tid; i < 4224; i += THREADS) dst[i] = src[i];
    }
    __syncthreads();
    {
        float acc[4][4];
#pragma unroll
        for (int i = 0; i < 4; i++)
#pragma unroll
            for (int j = 0; j < 4; j++) acc[i][j] = 0.f;

        const float4* ap = (const float4*)(s + S_A) + mi * 512 + lane;
        const float* wcol = s + S_W + (nq * 32 + g) * 132 + t * 2;
#pragma unroll
        for (int ks = 0; ks < 16; ks++) {
            float4 av = ap[ks * 32];
            uint32_t a[4] = { fau(av.x), fau(av.y), fau(av.z), fau(av.w) };
#pragma unroll
            for (int nt = 0; nt < 4; nt++) {
                float2 bv = *(const float2*)(wcol + nt * (8 * 132) + ks * 8);
                uint32_t bb[2] = { fau(bv.x), fau(bv.y) };
                mma8(acc[nt], a, bb);
            }
        }

        // stage result rows [64][132] in S_QK (P dead), then coalesced store
        const int r0 = mi * 16 + g;
#pragma unroll
        for (int nt = 0; nt < 4; nt++) {
            const int c0 = nq * 32 + nt * 8 + 2 * t;
#pragma unroll
            for (int e = 0; e < 4; e++) {
                int rr = r0 + ((e >> 1) << 3);
                int cc = c0 + (e & 1);
                s[S_QK + rr * 132 + cc] = acc[nt][e] + s[S_B + 384 + cc];
            }
        }
    }
    __syncthreads();
    {
        float4* ob = (float4*)(out + (size_t)b * (NTOK * CDIM));
        for (int i = tid; i < NTOK * 32; i += THREADS) {
            int r = i >> 5, c4 = i & 31;
            const float* p = s + S_QK + r * 132 + c4 * 4;
            ob[i] = make_float4(p[0], p[1], p[2], p[3]);
        }
    }
}

extern "C" void kernel_launch(void* const* d_in, const int* in_sizes, int n_in,
                              void* d_out, int out_size)
{
    const float* x          = (const float*)d_in[0];
    const float* mask       = (const float*)d_in[1];
    const float* qkv_w      = (const float*)d_in[2];
    const float* qkv_b      = (const float*)d_in[3];
    const float* proj_w     = (const float*)d_in[4];
    const float* proj_b     = (const float*)d_in[5];
    const float* bias_table = (const float*)d_in[6];
    float* out = (float*)d_out;

    const int B = in_sizes[0] / (NTOK * CDIM);   // 8192
    const int smem_bytes = SMEMF * (int)sizeof(float);

    prep_weights<<<(66048 + 255) / 256, 256>>>(qkv_w, qkv_b, proj_w, proj_b);
    prep_bm<<<(64 * 4 * 49 * 56 + 255) / 256, 256>>>(mask, bias_table);

    cudaFuncSetAttribute(wattn, cudaFuncAttributeMaxDynamicSharedMemorySize, smem_bytes);
    wattn<<<B, THREADS, smem_bytes>>>(x, out);
}

// round 6
// speedup vs baseline: 1.3656x; 1.3656x over previous
#include <cuda_runtime.h>
#include <cstdint>

#define NTOK 49
#define CDIM 128
#define NHEAD 4
#define NWIN 64
#define THREADS 512

// ---- persistent prepped buffers (filled by prep kernels each launch) ----
__device__ float g_qkvw[3 * 128 * 132];        // tf32, [j][132] natural k order, q-scale folded
__device__ float g_projw[128 * 132];           // tf32, [j][132]
__device__ float g_qkvb[512];                  // qkv_b (q part scaled) ++ proj_b
__device__ float g_bm[64 * 4 * 49 * 56];       // fused rel-pos-bias + mask, col-padded to 56

// ---- shared memory layout (float offsets) — identical to round 3 + bias tail ----
#define XS_STR 132
#define XS_OFF 0
#define XS_SZ  (64 * XS_STR)          // 8448
#define R2_OFF (XS_OFF + XS_SZ)       // 8448 : weight tile [128][132] OR attn [4][64][60]
#define R2_SZ  (128 * 132)            // 16896
#define WS_STR 132
#define AT_STR 60
#define AT_HSZ (64 * AT_STR)
#define QKV_OFF (R2_OFF + R2_SZ)      // 25344 : q/k/v [3][4][64][36]
#define QK_STR 36
#define QK_HSZ (64 * QK_STR)
#define QK_CSZ (NHEAD * QK_HSZ)
#define SB_OFF (QKV_OFF + 3 * QK_CSZ) // 52992
#define SMEM_FLOATS (SB_OFF + 512)    // 53504 floats = 214016 bytes

__device__ __forceinline__ float f2tf(float f) {
    uint32_t u;
    asm("cvt.rna.tf32.f32 %0, %1;" : "=r"(u) : "f"(f));
    return __uint_as_float(u);
}
__device__ __forceinline__ uint32_t fau(float f) { return __float_as_uint(f); }

__device__ __forceinline__ void mma8(float c[4], const uint32_t a[4], const uint32_t b[2]) {
    asm volatile(
        "mma.sync.aligned.m16n8k8.row.col.f32.tf32.tf32.f32 "
        "{%0,%1,%2,%3},{%4,%5,%6,%7},{%8,%9},{%0,%1,%2,%3};\n"
        : "+f"(c[0]), "+f"(c[1]), "+f"(c[2]), "+f"(c[3])
        : "r"(a[0]), "r"(a[1]), "r"(a[2]), "r"(a[3]), "r"(b[0]), "r"(b[1]));
}

// ================= prep kernels (once per launch, ~5 us total) =================
__global__ void prep_weights(const float* __restrict__ qkv_w, const float* __restrict__ qkv_b,
                             const float* __restrict__ proj_w, const float* __restrict__ proj_b)
{
    int idx = blockIdx.x * 256 + threadIdx.x;
    const float scale = 0.17677669529663687f;   // 32^-0.5
    if (idx < 49152) {
        int ch = idx >> 14;
        int j  = (idx >> 7) & 127;
        int k  = idx & 127;
        float v = qkv_w[(size_t)(ch * 128 + j) * 128 + k];
        if (ch == 0) v *= scale;
        g_qkvw[ch * 16896 + j * 132 + k] = f2tf(v);
    } else if (idx < 65536) {
        int i2 = idx - 49152;
        int j = i2 >> 7, k = i2 & 127;
        g_projw[j * 132 + k] = f2tf(proj_w[(size_t)j * 128 + k]);
    } else if (idx < 65536 + 384) {
        int i = idx - 65536;
        float v = qkv_b[i];
        if (i < 128) v *= scale;
        g_qkvb[i] = v;
    } else if (idx < 65536 + 512) {
        int i = idx - 65536;
        g_qkvb[i] = proj_b[i - 384];
    }
}

__global__ void prep_bm(const float* __restrict__ mask, const float* __restrict__ bias_table)
{
    int idx = blockIdx.x * 256 + threadIdx.x;
    if (idx >= 64 * 4 * 49 * 56) return;
    int j = idx % 56;
    int rest = idx / 56;
    int i = rest % 49; rest /= 49;
    int h = rest & 3;
    int w = rest >> 2;
    float v = 0.f;
    if (j < 49) {
        int ih = i / 7, iw = i - 7 * ih;
        int jh = j / 7, jw = j - 7 * jh;
        int ridx = (ih - jh + 6) * 13 + (iw - jw + 6);
        v = bias_table[ridx * 4 + h] + mask[(size_t)(w * 49 + i) * 49 + j];
    }
    g_bm[idx] = v;
}

// ================= main kernel (round-3 structure) =================
__global__ __launch_bounds__(THREADS, 1)
void window_attn_tc(const float* __restrict__ x, float* __restrict__ out)
{
    extern __shared__ float s[];
    float* xs = s + XS_OFF;           // [64][132] tf32: x tile, later attn-out tile
    float* r2 = s + R2_OFF;           // weight tile or attn scores
    float* sb = s + SB_OFF;           // biases

    const int tid  = threadIdx.x;
    const int wid  = tid >> 5;
    const int lane = tid & 31;
    const int g    = lane >> 2;
    const int t    = lane & 3;
    const int b    = blockIdx.x;

    // ---- Phase 1: load x tile (tf32), zero-pad rows 49..63 ; stage biases ----
    {
        const float4* xb = (const float4*)(x + (size_t)b * (NTOK * CDIM));
        for (int i = tid; i < 64 * 32; i += THREADS) {
            int r = i >> 5, c4 = i & 31;
            float4 v = (r < NTOK) ? xb[r * 32 + c4] : make_float4(0.f, 0.f, 0.f, 0.f);
            float* d = xs + r * XS_STR + c4 * 4;
            d[0] = f2tf(v.x); d[1] = f2tf(v.y); d[2] = f2tf(v.z); d[3] = f2tf(v.w);
        }
        sb[tid] = g_qkvb[tid];        // THREADS == 512 == bias count
    }
    __syncthreads();

    // ---- Phase 2: QKV = x @ qkv_w^T + b (scale pre-folded), 3 chunks ----
    for (int ch = 0; ch < 3; ch++) {
        {
            const float4* src = (const float4*)(g_qkvw + ch * 16896);
            float4* dst = (float4*)r2;
            for (int i = tid; i < 4224; i += THREADS) dst[i] = src[i];
        }
        __syncthreads();

        const int mi = wid & 3;
        const int nq = wid >> 2;
        const int r0 = mi * 16 + g;

        float acc[4][4];
#pragma unroll
        for (int i = 0; i < 4; i++)
#pragma unroll
            for (int j = 0; j < 4; j++) acc[i][j] = 0.f;

#pragma unroll
        for (int ks = 0; ks < 16; ks++) {
            const int k0 = ks * 8;
            const float* ar = xs + r0 * XS_STR + k0 + t;
            uint32_t a[4] = { fau(ar[0]), fau(ar[8 * XS_STR]),
                              fau(ar[4]), fau(ar[8 * XS_STR + 4]) };
#pragma unroll
            for (int nt = 0; nt < 4; nt++) {
                const float* br = r2 + (nq * 32 + nt * 8 + g) * WS_STR + k0 + t;
                uint32_t bb[2] = { fau(br[0]), fau(br[4]) };
                mma8(acc[nt], a, bb);
            }
        }

        // epilogue -> q/k/v smem (tf32); bias from smem, no scale mul
        {
            float* dst = s + QKV_OFF + ch * QK_CSZ;
            const float* bch = sb + ch * 128;
#pragma unroll
            for (int nt = 0; nt < 4; nt++) {
                const int c0 = nq * 32 + nt * 8 + 2 * t;
#pragma unroll
                for (int e = 0; e < 4; e++) {
                    const int rr = r0 + ((e >= 2) ? 8 : 0);
                    const int cc = c0 + (e & 1);
                    const int h = cc >> 5, dd = cc & 31;
                    dst[h * QK_HSZ + rr * QK_STR + dd] = f2tf(acc[nt][e] + bch[cc]);
                }
            }
        }
        __syncthreads();
    }

    // ---- Phase 3: scores = q k^T + fused(bias+mask) -> attn [4][64][60] ----
    {
        const int h  = wid >> 2;
        const int mi = wid & 3;
        const int r0 = mi * 16 + g;
        const float* qh = s + QKV_OFF + 0 * QK_CSZ + h * QK_HSZ;
        const float* kh = s + QKV_OFF + 1 * QK_CSZ + h * QK_HSZ;

        float acc[7][4];
#pragma unroll
        for (int i = 0; i < 7; i++)
#pragma unroll
            for (int j = 0; j < 4; j++) acc[i][j] = 0.f;

#pragma unroll
        for (int ks = 0; ks < 4; ks++) {
            const int k0 = ks * 8;
            const float* ar = qh + r0 * QK_STR + k0 + t;
            uint32_t a[4] = { fau(ar[0]), fau(ar[8 * QK_STR]),
                              fau(ar[4]), fau(ar[8 * QK_STR + 4]) };
#pragma unroll
            for (int nt = 0; nt < 7; nt++) {
                const float* br = kh + (nt * 8 + g) * QK_STR + k0 + t;
                uint32_t bb[2] = { fau(br[0]), fau(br[4]) };
                mma8(acc[nt], a, bb);
            }
        }

        float* at = r2 + h * AT_HSZ;
        const float* bmw = g_bm + (size_t)(b & (NWIN - 1)) * (4 * 49 * 56) + h * (49 * 56);
        const int rA = r0, rB = r0 + 8;
#pragma unroll
        for (int nt = 0; nt < 7; nt++) {
            const int c0 = nt * 8 + 2 * t;
#pragma unroll
            for (int e = 0; e < 4; e++) {
                const int rr = (e >= 2) ? rB : rA;
                const int jj = c0 + (e & 1);
                float v = 0.f;
                if (rr < NTOK && jj < NTOK)
                    v = acc[nt][e] + __ldg(bmw + rr * 56 + jj);
                at[rr * AT_STR + jj] = v;
            }
        }
    }
    __syncthreads();

    // ---- Phase 4: softmax per (h, i<49) row; recompute exp (no local array) ----
    if (tid < NHEAD * NTOK) {
        const int h = tid / NTOK;
        const int i = tid - h * NTOK;
        float* row = r2 + h * AT_HSZ + i * AT_STR;
        float m = row[0];
#pragma unroll
        for (int j = 1; j < NTOK; j++) m = fmaxf(m, row[j]);
        float ssum = 0.f;
#pragma unroll
        for (int j = 0; j < NTOK; j++) ssum += __expf(row[j] - m);
        const float inv = 1.0f / ssum;
#pragma unroll
        for (int j = 0; j < NTOK; j++) row[j] = f2tf(__expf(row[j] - m) * inv);
    }
    __syncthreads();

    // ---- Phase 5: o = attn @ v -> xs [64][132] (cols h*32+d), tf32 ----
    {
        const int h  = wid >> 2;
        const int mi = wid & 3;
        const int r0 = mi * 16 + g;
        const float* at = r2 + h * AT_HSZ;
        const float* vh = s + QKV_OFF + 2 * QK_CSZ + h * QK_HSZ;

        float acc[4][4];
#pragma unroll
        for (int i = 0; i < 4; i++)
#pragma unroll
            for (int j = 0; j < 4; j++) acc[i][j] = 0.f;

#pragma unroll
        for (int ks = 0; ks < 7; ks++) {
            const int k0 = ks * 8;
            const float* ar = at + r0 * AT_STR + k0 + t;
            uint32_t a[4] = { fau(ar[0]), fau(ar[8 * AT_STR]),
                              fau(ar[4]), fau(ar[8 * AT_STR + 4]) };
#pragma unroll
            for (int nt = 0; nt < 4; nt++) {
                const float* br = vh + (k0 + t) * QK_STR + nt * 8 + g;
                uint32_t bb[2] = { fau(br[0]), fau(br[4 * QK_STR]) };
                mma8(acc[nt], a, bb);
            }
        }
        __syncthreads();   // attn reads done before r2 is overwritten with proj_w

#pragma unroll
        for (int nt = 0; nt < 4; nt++) {
            const int c0 = nt * 8 + 2 * t;
#pragma unroll
            for (int e = 0; e < 4; e++) {
                const int rr = r0 + ((e >= 2) ? 8 : 0);
                const int dd = c0 + (e & 1);
                xs[rr * XS_STR + h * 32 + dd] = f2tf(acc[nt][e]);
            }
        }
    }
    __syncthreads();

    // ---- Phase 6: final = o @ proj_w^T + proj_b ----
    {
        const float4* src = (const float4*)g_projw;
        float4* dst = (float4*)r2;
        for (int i = tid; i < 4224; i += THREADS) dst[i] = src[i];
    }
    __syncthreads();
    {
        const int mi = wid & 3;
        const int nq = wid >> 2;
        const int r0 = mi * 16 + g;

        float acc[4][4];
#pragma unroll
        for (int i = 0; i < 4; i++)
#pragma unroll
            for (int j = 0; j < 4; j++) acc[i][j] = 0.f;

#pragma unroll
        for (int ks = 0; ks < 16; ks++) {
            const int k0 = ks * 8;
            const float* ar = xs + r0 * XS_STR + k0 + t;
            uint32_t a[4] = { fau(ar[0]), fau(ar[8 * XS_STR]),
                              fau(ar[4]), fau(ar[8 * XS_STR + 4]) };
#pragma unroll
            for (int nt = 0; nt < 4; nt++) {
                const float* br = r2 + (nq * 32 + nt * 8 + g) * WS_STR + k0 + t;
                uint32_t bb[2] = { fau(br[0]), fau(br[4]) };
                mma8(acc[nt], a, bb);
            }
        }

        // stage into smem (QKV region, free now) for coalesced global store
        float* os = s + QKV_OFF;      // [64][132]
#pragma unroll
        for (int nt = 0; nt < 4; nt++) {
            const int c0 = nq * 32 + nt * 8 + 2 * t;
#pragma unroll
            for (int e = 0; e < 4; e++) {
                const int rr = r0 + ((e >= 2) ? 8 : 0);
                const int cc = c0 + (e & 1);
                os[rr * XS_STR + cc] = acc[nt][e] + sb[384 + cc];
            }
        }
        __syncthreads();

        float4* ob = (float4*)(out + (size_t)b * (NTOK * CDIM));
        for (int i = tid; i < NTOK * 32; i += THREADS) {
            int r = i >> 5, c4 = i & 31;
            const float* p = os + r * XS_STR + c4 * 4;
            ob[i] = make_float4(p[0], p[1], p[2], p[3]);
        }
    }
}

extern "C" void kernel_launch(void* const* d_in, const int* in_sizes, int n_in,
                              void* d_out, int out_size)
{
    const float* x          = (const float*)d_in[0];
    const float* mask       = (const float*)d_in[1];
    const float* qkv_w      = (const float*)d_in[2];
    const float* qkv_b      = (const float*)d_in[3];
    const float* proj_w     = (const float*)d_in[4];
    const float* proj_b     = (const float*)d_in[5];
    const float* bias_table = (const float*)d_in[6];
    float* out = (float*)d_out;

    const int B = in_sizes[0] / (NTOK * CDIM);   // 8192
    const int smem_bytes = SMEM_FLOATS * (int)sizeof(float);

    prep_weights<<<(66048 + 255) / 256, 256>>>(qkv_w, qkv_b, proj_w, proj_b);
    prep_bm<<<(64 * 4 * 49 * 56 + 255) / 256, 256>>>(mask, bias_table);

    cudaFuncSetAttribute(window_attn_tc,
                         cudaFuncAttributeMaxDynamicSharedMemorySize, smem_bytes);

    window_attn_tc<<<B, THREADS, smem_bytes>>>(x, out);
}